// round 1
// baseline (speedup 1.0000x reference)
#include <cuda_runtime.h>

typedef unsigned long long u64;

#define NB      16
#define SS      4096
#define DD      512
#define D4      128          // float4 (16B) per row
#define HALO    19
#define CHUNK   64
#define RING    83           // CHUNK + HALO rows resident
#define TM      8            // rows per warp register tile
#define NWARPS  8
#define NTHR    256
#define NSEG    8
#define SEGLEN  512
#define NBLK    (NB * NSEG)
#define CNT_DIST 40815       // sum_{k=10}^{19} (4096 - k)

__device__ float2 g_part[NBLK];

// packed f32x2 FMA: 2 fp32 FMAs per instruction (ptxas won't auto-fuse)
__device__ __forceinline__ u64 ffma2(u64 a, u64 b, u64 c) {
    u64 d;
    asm("fma.rn.f32x2 %0, %1, %2, %3;" : "=l"(d) : "l"(a), "l"(b), "l"(c));
    return d;
}
// horizontal sum of a packed f32x2
__device__ __forceinline__ float hsum2(u64 v) {
    float x, y;
    asm("mov.b64 {%0,%1}, %2;" : "=f"(x), "=f"(y) : "l"(v));
    return x + y;
}
__device__ __forceinline__ float wred(float v) {
    v += __shfl_xor_sync(0xffffffffu, v, 16);
    v += __shfl_xor_sync(0xffffffffu, v, 8);
    v += __shfl_xor_sync(0xffffffffu, v, 4);
    v += __shfl_xor_sync(0xffffffffu, v, 2);
    v += __shfl_xor_sync(0xffffffffu, v, 1);
    return v;
}

extern __shared__ ulonglong2 smem[];   // RING * D4 entries of 16B

__global__ void __launch_bounds__(NTHR, 1)
tcl_main(const float* __restrict__ hs) {
    const int seg  = blockIdx.x;
    const int b    = blockIdx.y;
    const int t0   = seg * SEGLEN;
    const int tid  = threadIdx.x;
    const int wid  = tid >> 5;
    const int lane = tid & 31;

    const float4* __restrict__ hb4 =
        reinterpret_cast<const float4*>(hs) + (size_t)b * SS * D4;

    float accA = 0.f;   // sum of adjacent sims
    float accD = 0.f;   // sum of relu(0.5 - sim) for k in [10,19]

    for (int ci = 0; ci < SEGLEN / CHUNK; ++ci) {
        const int c0 = t0 + ci * CHUNK;
        // ring-buffer: first chunk loads all RING rows, later chunks only CHUNK new rows
        const int loadLo = ci ? (c0 + HALO) : c0;
        const int nrows  = c0 + RING - loadLo;

        for (int idx = tid; idx < nrows * D4; idx += NTHR) {
            int rr = idx >> 7;
            int cc = idx & 127;
            int r  = loadLo + rr;
            int slot = (r - t0) % RING;
            float4 v = (r < SS) ? hb4[(size_t)r * D4 + cc]
                                : make_float4(0.f, 0.f, 0.f, 0.f);
            reinterpret_cast<float4*>(smem)[slot * D4 + cc] = v;
        }
        __syncthreads();

        const int tt = c0 + wid * TM;
        const int sb = (tt - t0) % RING;

        // register tile: 8 rows x 16 floats/lane (as 8 packed f32x2 per row)
        ulonglong2 a[TM][4];
        float invn[TM];
#pragma unroll
        for (int i = 0; i < TM; ++i) {
            int sl = sb + i; if (sl >= RING) sl -= RING;
            const ulonglong2* row = smem + sl * D4;
#pragma unroll
            for (int j = 0; j < 4; ++j) a[i][j] = row[lane + 32 * j];
            u64 sp = 0ull;
#pragma unroll
            for (int j = 0; j < 4; ++j) {
                sp = ffma2(a[i][j].x, a[i][j].x, sp);
                sp = ffma2(a[i][j].y, a[i][j].y, sp);
            }
            float ssv = wred(hsum2(sp));
            invn[i] = rsqrtf(ssv);
        }

        // stream partner rows r = tt+1 .. tt+26; each serves all shifts hitting the tile
#pragma unroll
        for (int d = 1; d <= TM + HALO - 1; ++d) {
            int r = tt + d;
            if (r < SS) {                 // warp-uniform predicate
                int sl = sb + d; if (sl >= RING) sl -= RING;
                const ulonglong2* row = smem + sl * D4;
                ulonglong2 s0 = row[lane];
                ulonglong2 s1 = row[lane + 32];
                ulonglong2 s2 = row[lane + 64];
                ulonglong2 s3 = row[lane + 96];

                u64 sp = 0ull;
                sp = ffma2(s0.x, s0.x, sp); sp = ffma2(s0.y, s0.y, sp);
                sp = ffma2(s1.x, s1.x, sp); sp = ffma2(s1.y, s1.y, sp);
                sp = ffma2(s2.x, s2.x, sp); sp = ffma2(s2.y, s2.y, sp);
                sp = ffma2(s3.x, s3.x, sp); sp = ffma2(s3.y, s3.y, sp);
                float invr = rsqrtf(wred(hsum2(sp)));

#pragma unroll
                for (int ki = 0; ki < 11; ++ki) {
                    const int k = (ki == 0) ? 1 : (9 + ki);   // {1,10..19}
                    const int i = d - k;
                    if (0 <= i && i < TM) {                   // compile-time pruned
                        u64 qp = 0ull;
                        qp = ffma2(a[i][0].x, s0.x, qp); qp = ffma2(a[i][0].y, s0.y, qp);
                        qp = ffma2(a[i][1].x, s1.x, qp); qp = ffma2(a[i][1].y, s1.y, qp);
                        qp = ffma2(a[i][2].x, s2.x, qp); qp = ffma2(a[i][2].y, s2.y, qp);
                        qp = ffma2(a[i][3].x, s3.x, qp); qp = ffma2(a[i][3].y, s3.y, qp);
                        float q   = wred(hsum2(qp));
                        float sim = q * (invn[i] * invr);
                        if (k == 1) accA += sim;
                        else        accD += fmaxf(0.5f - sim, 0.f);
                    }
                }
            }
        }
        __syncthreads();
    }

    __shared__ float rA[NWARPS], rD[NWARPS];
    if (lane == 0) { rA[wid] = accA; rD[wid] = accD; }
    __syncthreads();
    if (tid == 0) {
        float sA = 0.f, sD = 0.f;
#pragma unroll
        for (int w = 0; w < NWARPS; ++w) { sA += rA[w]; sD += rD[w]; }
        g_part[b * NSEG + seg] = make_float2(sA, sD);
    }
}

__global__ void tcl_final(float* __restrict__ out) {
    __shared__ float sa[4], sd[4];
    int tid = threadIdx.x;   // 128 threads
    float a = 0.f, dd = 0.f;
    if (tid < NBLK) { float2 p = g_part[tid]; a = p.x; dd = p.y; }
    a  = wred(a);
    dd = wred(dd);
    if ((tid & 31) == 0) { sa[tid >> 5] = a; sd[tid >> 5] = dd; }
    __syncthreads();
    if (tid == 0) {
        float sA = sa[0] + sa[1] + sa[2] + sa[3];
        float sD = sd[0] + sd[1] + sd[2] + sd[3];
        float adj  = 1.f - sA / ((float)NB * (float)(SS - 1));
        float dist = sD / ((float)NB * (float)CNT_DIST);
        out[0] = adj + dist;
    }
}

extern "C" void kernel_launch(void* const* d_in, const int* in_sizes, int n_in,
                              void* d_out, int out_size) {
    (void)in_sizes; (void)n_in; (void)out_size;
    const float* hs = (const float*)d_in[0];

    const size_t shmem = (size_t)RING * D4 * sizeof(ulonglong2);  // 169,984 B
    cudaFuncSetAttribute(tcl_main, cudaFuncAttributeMaxDynamicSharedMemorySize,
                         (int)shmem);

    dim3 grid(NSEG, NB);
    tcl_main<<<grid, NTHR, shmem>>>(hs);
    tcl_final<<<1, 128>>>((float*)d_out);
}